// round 11
// baseline (speedup 1.0000x reference)
#include <cuda_runtime.h>
#include <cuda_fp16.h>
#include <cstdint>

// ChebConv K=8 on GB300 — Clenshaw form, 3 kernels total:
//   init : zero state + dtype detect + pack Wcat^T mma fragments
//   gemmz: Z = x @ Wcat  (fp32 A read, fp16 mma, [50000,128]x[128,512])
//   mega : hist -> CSR scan -> scatter -> 6 Clenshaw props -> final
//          single-wave persistent grid with software grid barriers

#define N_NODES 50000
#define N_EDGES 800000
#define EPAD    (N_EDGES + 4 * N_NODES)
#define F_IN    128
#define F_OUT   64
#define KORD    8
#define ZTOT    (KORD * F_OUT)               // 512
#define GEMM_BLOCKS ((N_NODES + 31) / 32)    // 1563
#define GRID_MEGA 592                        // = 148 SMs x 4 blocks
#define THR_MEGA  256
#define GSZ       (GRID_MEGA * THR_MEGA)     // 151552
#define NWARP_MEGA (GRID_MEGA * (THR_MEGA / 32))  // 4736

// ---- scratch (static device globals; no allocations) ----
__device__ __align__(16) __half g_T[(size_t)N_NODES * ZTOT];  // Z/b slots, 64 each
__device__ __align__(16) uint2  g_Wpack[8 * 64 * 32];         // [ks][ntile][lane]
__device__ int      g_is64;
__device__ unsigned g_barrier;
__device__ int   g_cnt[N_NODES];
__device__ int   g_deg[N_NODES];
__device__ float g_dis[N_NODES];
__device__ int   g_rowptr[N_NODES + 1];
__device__ int   g_cursor[N_NODES];
__device__ int   g_bsum[GRID_MEGA];
__device__ __align__(8) int2 g_edge[EPAD];   // {src, float_bits(w)}

// =================== helpers ===============================================
__device__ __forceinline__ void mma16816(float* c, const uint32_t* a, const uint32_t* b) {
    asm volatile(
        "mma.sync.aligned.m16n8k16.row.col.f32.f16.f16.f32 "
        "{%0,%1,%2,%3}, {%4,%5,%6,%7}, {%8,%9}, {%0,%1,%2,%3};"
        : "+f"(c[0]), "+f"(c[1]), "+f"(c[2]), "+f"(c[3])
        : "r"(a[0]), "r"(a[1]), "r"(a[2]), "r"(a[3]), "r"(b[0]), "r"(b[1]));
}
__device__ __forceinline__ uint32_t pack_h2(float a, float b) {
    __half2 h = __floats2half2_rn(a, b);
    return *reinterpret_cast<uint32_t*>(&h);
}
__device__ __forceinline__ float2 unpack_h2(uint32_t q) {
    __half2 h = *reinterpret_cast<__half2*>(&q);
    return __half22float2(h);
}
__device__ __forceinline__ void decode_edge(const void* ei, int e, int& s, int& d) {
    if (g_is64) {
        const long long* p = (const long long*)ei;
        s = (int)p[e]; d = (int)p[N_EDGES + e];
    } else {
        const int* p = (const int*)ei;
        s = p[e]; d = p[N_EDGES + e];
    }
    s = min(max(s, 0), N_NODES - 1);
    d = min(max(d, 0), N_NODES - 1);
}
// software grid barrier: all GRID_MEGA blocks resident (single wave by
// construction), monotonic counter (zeroed in init each launch).
__device__ __forceinline__ void grid_sync(unsigned& target) {
    __syncthreads();
    if (threadIdx.x == 0) {
        __threadfence();
        atomicAdd(&g_barrier, 1u);
        target += GRID_MEGA;
        while (*(volatile unsigned*)&g_barrier < target) { }
    }
    __syncthreads();
    __threadfence();
}

// ============================ init =========================================
// zero histograms + barrier, dtype detect, pack Wcat^T fragments
__global__ void init_kernel(const unsigned int* __restrict__ p, const float* __restrict__ W) {
    int i = blockIdx.x * blockDim.x + threadIdx.x;
    if (blockIdx.x == 0 && threadIdx.x < 32) {
        int lane = threadIdx.x;
        bool bad = false;
        #pragma unroll
        for (int j = 0; j < 8; j++)
            if (p[2 * (lane * 8 + j) + 1] != 0u) bad = true;
        unsigned m = __ballot_sync(0xffffffffu, bad);
        if (lane == 0) { g_is64 = (m == 0u) ? 1 : 0; g_barrier = 0u; }
    }
    if (i < N_NODES) { g_cnt[i] = 0; g_deg[i] = 0; }
    if (i < 8 * 64 * 32) {
        int lane = i & 31, nt = (i >> 5) & 63, ks = i >> 11;
        int n  = nt * 8 + (lane >> 2);               // col 0..511
        int k0 = ks * 16 + (lane & 3) * 2;
        int o = n >> 6, j2 = n & 63;
        const float* Wb = W + (size_t)o * (F_IN * F_OUT) + j2;
        float v00 = Wb[(size_t)(k0    ) * 64];
        float v01 = Wb[(size_t)(k0 + 1) * 64];
        float v10 = Wb[(size_t)(k0 + 8) * 64];
        float v11 = Wb[(size_t)(k0 + 9) * 64];
        uint2 pk;
        pk.x = pack_h2(v00, v01);
        pk.y = pack_h2(v10, v11);
        g_Wpack[i] = pk;
    }
}

// ===================== GEMM Z = x @ Wcat (mma.sync fp16) ===================
// 256 threads = 8 warps; rows [blk*32,+32); warp w -> cols [w*64,+64)
__global__ void __launch_bounds__(256) gemmz_kernel(const float* __restrict__ x) {
    int wid = threadIdx.x >> 5, lane = threadIdx.x & 31;
    int row0 = blockIdx.x * 32;
    int r  = lane >> 2;
    int cc = (lane & 3) * 2;

    int rr[4];
    rr[0] = min(row0      + r, N_NODES - 1);
    rr[1] = min(row0 +  8 + r, N_NODES - 1);
    rr[2] = min(row0 + 16 + r, N_NODES - 1);
    rr[3] = min(row0 + 24 + r, N_NODES - 1);

    float acc[2][8][4];
    #pragma unroll
    for (int m = 0; m < 2; m++)
        #pragma unroll
        for (int j = 0; j < 8; j++)
            #pragma unroll
            for (int q = 0; q < 4; q++) acc[m][j][q] = 0.f;

    #pragma unroll
    for (int ks = 0; ks < 8; ks++) {                  // K = 128
        int kt = ks * 16;
        uint32_t ah[2][4];
        #pragma unroll
        for (int m = 0; m < 2; m++) {
            const float* p0 = x + (size_t)rr[2 * m    ] * F_IN + kt;
            const float* p1 = x + (size_t)rr[2 * m + 1] * F_IN + kt;
            float2 a0 = __ldg((const float2*)(p0 + cc));
            float2 a1 = __ldg((const float2*)(p1 + cc));
            float2 a2 = __ldg((const float2*)(p0 + cc + 8));
            float2 a3 = __ldg((const float2*)(p1 + cc + 8));
            ah[m][0] = pack_h2(a0.x, a0.y);
            ah[m][1] = pack_h2(a1.x, a1.y);
            ah[m][2] = pack_h2(a2.x, a2.y);
            ah[m][3] = pack_h2(a3.x, a3.y);
        }
        const uint2* wp = g_Wpack + ((size_t)ks * 64 + wid * 8) * 32 + lane;
        #pragma unroll
        for (int j = 0; j < 8; j++) {
            uint2 bp = __ldg(wp + j * 32);
            uint32_t bh[2] = {bp.x, bp.y};
            mma16816(acc[0][j], ah[0], bh);
            mma16816(acc[1][j], ah[1], bh);
        }
    }
    #pragma unroll
    for (int m = 0; m < 2; m++) {
        int row_a = row0 + m * 16 + r;
        int row_b = row_a + 8;
        #pragma unroll
        for (int j = 0; j < 8; j++) {
            int col = wid * 64 + j * 8 + cc;
            if (row_a < N_NODES)
                *(uint32_t*)&g_T[(size_t)row_a * ZTOT + col] = pack_h2(acc[m][j][0], acc[m][j][1]);
            if (row_b < N_NODES)
                *(uint32_t*)&g_T[(size_t)row_b * ZTOT + col] = pack_h2(acc[m][j][2], acc[m][j][3]);
        }
    }
}

// ===================== mega: graph build + Clenshaw ========================
// prop for one node (warp-collective): acc = L_hat b(slot_g) over this node
template<int SLOT_G, int SLOT_B2, int SLOT_Z>
__device__ __forceinline__ void cheb_node(int n, int lane) {
    int beg = g_rowptr[n], end = g_rowptr[n + 1];
    int cg = SLOT_G * F_OUT + lane * 2;
    float2 acc = make_float2(0.f, 0.f);
    #pragma unroll 2
    for (int e = beg; e < end; e += 4) {
        int2 ed0 = __ldg(&g_edge[e]);
        int2 ed1 = __ldg(&g_edge[e + 1]);
        int2 ed2 = __ldg(&g_edge[e + 2]);
        int2 ed3 = __ldg(&g_edge[e + 3]);
        uint32_t q0 = *(const uint32_t*)(g_T + (size_t)ed0.x * ZTOT + cg);
        uint32_t q1 = *(const uint32_t*)(g_T + (size_t)ed1.x * ZTOT + cg);
        uint32_t q2 = *(const uint32_t*)(g_T + (size_t)ed2.x * ZTOT + cg);
        uint32_t q3 = *(const uint32_t*)(g_T + (size_t)ed3.x * ZTOT + cg);
        float w0 = __int_as_float(ed0.y), w1 = __int_as_float(ed1.y);
        float w2 = __int_as_float(ed2.y), w3 = __int_as_float(ed3.y);
        float2 v0 = unpack_h2(q0), v1 = unpack_h2(q1);
        float2 v2 = unpack_h2(q2), v3 = unpack_h2(q3);
        acc.x += w0 * v0.x + w1 * v1.x + w2 * v2.x + w3 * v3.x;
        acc.y += w0 * v0.y + w1 * v1.y + w2 * v2.y + w3 * v3.y;
    }
    size_t rbase = (size_t)n * ZTOT;
    float2 z = unpack_h2(*(const uint32_t*)(g_T + rbase + SLOT_Z * F_OUT + lane * 2));
    float2 r;
    if (SLOT_B2 >= 0) {
        float2 b2 = unpack_h2(*(const uint32_t*)(g_T + rbase + SLOT_B2 * F_OUT + lane * 2));
        r.x = 2.f * acc.x - b2.x + z.x;
        r.y = 2.f * acc.y - b2.y + z.y;
    } else {
        r.x = 2.f * acc.x + z.x;
        r.y = 2.f * acc.y + z.y;
    }
    *(uint32_t*)(g_T + rbase + SLOT_Z * F_OUT + lane * 2) = pack_h2(r.x, r.y);
}

__device__ __forceinline__ void final_node(int n, int lane,
        const float* __restrict__ bias, float* __restrict__ out) {
    int beg = g_rowptr[n], end = g_rowptr[n + 1];
    int cg = 1 * F_OUT + lane * 2;
    float2 acc = make_float2(0.f, 0.f);
    #pragma unroll 2
    for (int e = beg; e < end; e += 4) {
        int2 ed0 = __ldg(&g_edge[e]);
        int2 ed1 = __ldg(&g_edge[e + 1]);
        int2 ed2 = __ldg(&g_edge[e + 2]);
        int2 ed3 = __ldg(&g_edge[e + 3]);
        uint32_t q0 = *(const uint32_t*)(g_T + (size_t)ed0.x * ZTOT + cg);
        uint32_t q1 = *(const uint32_t*)(g_T + (size_t)ed1.x * ZTOT + cg);
        uint32_t q2 = *(const uint32_t*)(g_T + (size_t)ed2.x * ZTOT + cg);
        uint32_t q3 = *(const uint32_t*)(g_T + (size_t)ed3.x * ZTOT + cg);
        float w0 = __int_as_float(ed0.y), w1 = __int_as_float(ed1.y);
        float w2 = __int_as_float(ed2.y), w3 = __int_as_float(ed3.y);
        float2 v0 = unpack_h2(q0), v1 = unpack_h2(q1);
        float2 v2 = unpack_h2(q2), v3 = unpack_h2(q3);
        acc.x += w0 * v0.x + w1 * v1.x + w2 * v2.x + w3 * v3.x;
        acc.y += w0 * v0.y + w1 * v1.y + w2 * v2.y + w3 * v3.y;
    }
    size_t rbase = (size_t)n * ZTOT;
    float2 z0 = unpack_h2(*(const uint32_t*)(g_T + rbase + 0 * F_OUT + lane * 2));
    float2 b2 = unpack_h2(*(const uint32_t*)(g_T + rbase + 2 * F_OUT + lane * 2));
    float2 bv = *(const float2*)(bias + lane * 2);
    float2 o;
    o.x = fmaxf(acc.x - b2.x + z0.x + bv.x, 0.f);
    o.y = fmaxf(acc.y - b2.y + z0.y + bv.y, 0.f);
    *(float2*)(out + (size_t)n * F_OUT + lane * 2) = o;
}

__global__ void __launch_bounds__(THR_MEGA, 4) mega_kernel(
        const void* __restrict__ ei,
        const float* __restrict__ bias, float* __restrict__ out) {
    __shared__ int s_w[8];
    __shared__ int s_boff;
    unsigned target = 0;
    int tid = threadIdx.x, lane = tid & 31, wid = tid >> 5;
    int gtid = blockIdx.x * THR_MEGA + tid;
    int wgid = blockIdx.x * (THR_MEGA / 32) + wid;

    // ---- phase H: degree histograms ----
    for (int e = gtid; e < N_EDGES; e += GSZ) {
        int s, d;
        decode_edge(ei, e, s, d);
        atomicAdd(&g_deg[s], 1);
        atomicAdd(&g_cnt[d], 1);
    }
    grid_sync(target);

    // ---- phase S1: per-block scan of padded counts (+dis) ----
    int i = gtid;                       // one element per thread (GSZ > N_NODES)
    int cnt = 0, v = 0;
    if (i < N_NODES) {
        int d = g_deg[i];
        g_dis[i] = (d > 0) ? rsqrtf((float)d) : 0.0f;
        cnt = g_cnt[i];
        v = (cnt + 3) & ~3;
    }
    int x = v;
    #pragma unroll
    for (int off = 1; off < 32; off <<= 1) {
        int t = __shfl_up_sync(0xffffffffu, x, off);
        if (lane >= off) x += t;
    }
    if (lane == 31) s_w[wid] = x;
    __syncthreads();
    if (wid == 0) {
        int y = (lane < 8) ? s_w[lane] : 0;
        #pragma unroll
        for (int off = 1; off < 8; off <<= 1) {
            int t = __shfl_up_sync(0xffffffffu, y, off);
            if (lane >= off) y += t;
        }
        if (lane < 8) s_w[lane] = y;
    }
    __syncthreads();
    int lexcl = x - v + (wid > 0 ? s_w[wid - 1] : 0);
    if (tid == 0) g_bsum[blockIdx.x] = s_w[7];
    grid_sync(target);

    // ---- phase S2: block offset (reduce own prefix) + finalize rowptr ----
    {
        int s = 0;
        for (int bb = tid; bb < (int)blockIdx.x; bb += THR_MEGA) s += g_bsum[bb];
        #pragma unroll
        for (int off = 16; off >= 1; off >>= 1) s += __shfl_down_sync(0xffffffffu, s, off);
        if (lane == 0) s_w[wid] = s;
        __syncthreads();
        if (tid == 0) {
            int tot = 0;
            #pragma unroll
            for (int k = 0; k < 8; k++) tot += s_w[k];
            s_boff = tot;
            if (blockIdx.x == GRID_MEGA - 1)
                g_rowptr[N_NODES] = tot + g_bsum[blockIdx.x];
        }
        __syncthreads();
    }
    if (i < N_NODES) {
        int val = s_boff + lexcl;
        g_rowptr[i] = val;
        g_cursor[i] = val;
        int cntp = (cnt + 3) & ~3;
        for (int j = cnt; j < cntp; j++)
            g_edge[val + j] = make_int2(0, 0);
    }
    grid_sync(target);

    // ---- phase SC: scatter edges into padded CSR ----
    for (int e = gtid; e < N_EDGES; e += GSZ) {
        int s, d;
        decode_edge(ei, e, s, d);
        float w = -g_dis[s] * g_dis[d];
        int pos = atomicAdd(&g_cursor[d], 1);
        g_edge[pos] = make_int2(s, __float_as_int(w));
    }
    grid_sync(target);

    // ---- Clenshaw: b_7 = Z_7; b_k = 2 L b_{k+1} - b_{k+2} + Z_k ----
    for (int n = wgid; n < N_NODES; n += NWARP_MEGA) cheb_node<7, -1, 6>(n, lane);
    grid_sync(target);
    for (int n = wgid; n < N_NODES; n += NWARP_MEGA) cheb_node<6,  7, 5>(n, lane);
    grid_sync(target);
    for (int n = wgid; n < N_NODES; n += NWARP_MEGA) cheb_node<5,  6, 4>(n, lane);
    grid_sync(target);
    for (int n = wgid; n < N_NODES; n += NWARP_MEGA) cheb_node<4,  5, 3>(n, lane);
    grid_sync(target);
    for (int n = wgid; n < N_NODES; n += NWARP_MEGA) cheb_node<3,  4, 2>(n, lane);
    grid_sync(target);
    for (int n = wgid; n < N_NODES; n += NWARP_MEGA) cheb_node<2,  3, 1>(n, lane);
    grid_sync(target);
    // out = relu(L b_1 - b_2 + Z_0 + bias)
    for (int n = wgid; n < N_NODES; n += NWARP_MEGA) final_node(n, lane, bias, out);
}

// ---------------------------------------------------------------------------
extern "C" void kernel_launch(void* const* d_in, const int* in_sizes, int n_in,
                              void* d_out, int out_size) {
    const float* x  = (const float*)d_in[0];
    const void*  ei = d_in[1];
    const float* W  = (const float*)d_in[2];
    const float* b  = (const float*)d_in[3];
    float*       out = (float*)d_out;

    init_kernel<<<(N_NODES + 255) / 256, 256>>>((const unsigned int*)ei, W);
    gemmz_kernel<<<GEMM_BLOCKS, 256>>>(x);
    mega_kernel<<<GRID_MEGA, THR_MEGA>>>(ei, b, out);
}

// round 12
// speedup vs baseline: 1.1741x; 1.1741x over previous
#include <cuda_runtime.h>
#include <cuda_fp16.h>
#include <cstdint>

// ChebConv K=8 on GB300 — Clenshaw form (12 launches):
//   init : zero + dtype detect + pack Wcat^T mma fragments
//   hist -> scan1 -> scanf (fused scan2+scan3) -> scatter : padded CSR by dst
//   gemmz: Z = x @ Wcat (fp32 A read, fp16 mma)
//   6x cheb + final : b_k = 2 L_hat b_{k+1} - b_{k+2} + Z_k (64-wide props)

#define N_NODES 50000
#define N_EDGES 800000
#define EPAD    (N_EDGES + 4 * N_NODES)
#define F_IN    128
#define F_OUT   64
#define KORD    8
#define ZTOT    (KORD * F_OUT)               // 512
#define SCAN_BLK 1024
#define NBLK    ((N_NODES + SCAN_BLK - 1) / SCAN_BLK)   // 49
#define GEMM_BLOCKS ((N_NODES + 31) / 32)    // 1563

// ---- scratch (static device globals; no allocations) ----
__device__ __align__(16) __half g_T[(size_t)N_NODES * ZTOT];  // Z/b slots, 64 each
__device__ __align__(16) uint2  g_Wpack[8 * 64 * 32];         // [ks][ntile][lane]
__device__ int   g_is64;
__device__ int   g_cnt[N_NODES];
__device__ int   g_deg[N_NODES];
__device__ float g_dis[N_NODES];
__device__ int   g_rowptr[N_NODES + 1];
__device__ int   g_cursor[N_NODES];
__device__ int   g_bsum[NBLK];
__device__ __align__(8) int2 g_edge[EPAD];   // {src, float_bits(w)}

// =================== helpers ===============================================
__device__ __forceinline__ void mma16816(float* c, const uint32_t* a, const uint32_t* b) {
    asm volatile(
        "mma.sync.aligned.m16n8k16.row.col.f32.f16.f16.f32 "
        "{%0,%1,%2,%3}, {%4,%5,%6,%7}, {%8,%9}, {%0,%1,%2,%3};"
        : "+f"(c[0]), "+f"(c[1]), "+f"(c[2]), "+f"(c[3])
        : "r"(a[0]), "r"(a[1]), "r"(a[2]), "r"(a[3]), "r"(b[0]), "r"(b[1]));
}
__device__ __forceinline__ uint32_t pack_h2(float a, float b) {
    __half2 h = __floats2half2_rn(a, b);
    return *reinterpret_cast<uint32_t*>(&h);
}
__device__ __forceinline__ float2 unpack_h2(uint32_t q) {
    __half2 h = *reinterpret_cast<__half2*>(&q);
    return __half22float2(h);
}
__device__ __forceinline__ void decode_edge(const void* ei, int e, int& s, int& d) {
    if (g_is64) {
        const long long* p = (const long long*)ei;
        s = (int)p[e]; d = (int)p[N_EDGES + e];
    } else {
        const int* p = (const int*)ei;
        s = p[e]; d = p[N_EDGES + e];
    }
    s = min(max(s, 0), N_NODES - 1);
    d = min(max(d, 0), N_NODES - 1);
}

// ============================ preprocessing ================================
// zero histograms, dtype detect, pack Wcat^T fragments
__global__ void init_kernel(const unsigned int* __restrict__ p, const float* __restrict__ W) {
    int i = blockIdx.x * blockDim.x + threadIdx.x;
    if (blockIdx.x == 0 && threadIdx.x < 32) {
        int lane = threadIdx.x;
        bool bad = false;
        #pragma unroll
        for (int j = 0; j < 8; j++)
            if (p[2 * (lane * 8 + j) + 1] != 0u) bad = true;
        unsigned m = __ballot_sync(0xffffffffu, bad);
        if (lane == 0) g_is64 = (m == 0u) ? 1 : 0;
    }
    if (i < N_NODES) { g_cnt[i] = 0; g_deg[i] = 0; }
    if (i < 8 * 64 * 32) {
        int lane = i & 31, nt = (i >> 5) & 63, ks = i >> 11;
        int n  = nt * 8 + (lane >> 2);               // col 0..511
        int k0 = ks * 16 + (lane & 3) * 2;
        int o = n >> 6, j2 = n & 63;
        const float* Wb = W + (size_t)o * (F_IN * F_OUT) + j2;
        float v00 = Wb[(size_t)(k0    ) * 64];
        float v01 = Wb[(size_t)(k0 + 1) * 64];
        float v10 = Wb[(size_t)(k0 + 8) * 64];
        float v11 = Wb[(size_t)(k0 + 9) * 64];
        uint2 pk;
        pk.x = pack_h2(v00, v01);
        pk.y = pack_h2(v10, v11);
        g_Wpack[i] = pk;
    }
}
__global__ void hist_kernel(const void* __restrict__ ei) {
    int e = blockIdx.x * blockDim.x + threadIdx.x;
    if (e < N_EDGES) {
        int s, d;
        decode_edge(ei, e, s, d);
        atomicAdd(&g_deg[s], 1);
        atomicAdd(&g_cnt[d], 1);
    }
}
__global__ void scan1_kernel() {
    __shared__ int wsum[32];
    int tid = threadIdx.x, lane = tid & 31, wid = tid >> 5;
    int i = blockIdx.x * SCAN_BLK + tid;
    int v = 0;
    if (i < N_NODES) {
        int d = g_deg[i];
        g_dis[i] = (d > 0) ? rsqrtf((float)d) : 0.0f;
        v = (g_cnt[i] + 3) & ~3;             // pad row to multiple of 4
    }
    int x = v;
    #pragma unroll
    for (int off = 1; off < 32; off <<= 1) {
        int t = __shfl_up_sync(0xffffffffu, x, off);
        if (lane >= off) x += t;
    }
    if (lane == 31) wsum[wid] = x;
    __syncthreads();
    if (wid == 0) {
        int y = wsum[lane];
        #pragma unroll
        for (int off = 1; off < 32; off <<= 1) {
            int t = __shfl_up_sync(0xffffffffu, y, off);
            if (lane >= off) y += t;
        }
        wsum[lane] = y;
    }
    __syncthreads();
    int excl = x - v + (wid > 0 ? wsum[wid - 1] : 0);
    if (i < N_NODES) g_rowptr[i] = excl;     // local (intra-block) prefix
    if (tid == 0) g_bsum[blockIdx.x] = wsum[31];
}
// fused scan2+scan3: each block locally sums prior block aggregates (49 ints),
// finalizes rowptr/cursor, pre-fills padding edges
__global__ void __launch_bounds__(SCAN_BLK) scanf_kernel() {
    __shared__ int s_boff;
    int tid = threadIdx.x;
    if (tid == 0) {
        int off = 0;
        #pragma unroll 7
        for (int b = 0; b < (int)blockIdx.x; b++) off += g_bsum[b];
        s_boff = off;
        if (blockIdx.x == NBLK - 1) g_rowptr[N_NODES] = off + g_bsum[blockIdx.x];
    }
    __syncthreads();
    int i = blockIdx.x * SCAN_BLK + tid;
    if (i < N_NODES) {
        int val = g_rowptr[i] + s_boff;
        g_rowptr[i] = val;
        g_cursor[i] = val;
        int cnt  = g_cnt[i];
        int cntp = (cnt + 3) & ~3;
        for (int j = cnt; j < cntp; j++)
            g_edge[val + j] = make_int2(0, 0);
    }
}
__global__ void scatter_kernel(const void* __restrict__ ei) {
    int e = blockIdx.x * blockDim.x + threadIdx.x;
    if (e < N_EDGES) {
        int s, d;
        decode_edge(ei, e, s, d);
        float w = -g_dis[s] * g_dis[d];
        int pos = atomicAdd(&g_cursor[d], 1);
        g_edge[pos] = make_int2(s, __float_as_int(w));
    }
}

// ===================== GEMM Z = x @ Wcat (mma.sync fp16) ===================
// 256 threads = 8 warps; rows [blk*32,+32); warp w -> cols [w*64,+64)
__global__ void __launch_bounds__(256) gemmz_kernel(const float* __restrict__ x) {
    int wid = threadIdx.x >> 5, lane = threadIdx.x & 31;
    int row0 = blockIdx.x * 32;
    int r  = lane >> 2;
    int cc = (lane & 3) * 2;

    int rr[4];
    rr[0] = min(row0      + r, N_NODES - 1);
    rr[1] = min(row0 +  8 + r, N_NODES - 1);
    rr[2] = min(row0 + 16 + r, N_NODES - 1);
    rr[3] = min(row0 + 24 + r, N_NODES - 1);

    float acc[2][8][4];
    #pragma unroll
    for (int m = 0; m < 2; m++)
        #pragma unroll
        for (int j = 0; j < 8; j++)
            #pragma unroll
            for (int q = 0; q < 4; q++) acc[m][j][q] = 0.f;

    #pragma unroll
    for (int ks = 0; ks < 8; ks++) {                  // K = 128
        int kt = ks * 16;
        uint32_t ah[2][4];
        #pragma unroll
        for (int m = 0; m < 2; m++) {
            const float* p0 = x + (size_t)rr[2 * m    ] * F_IN + kt;
            const float* p1 = x + (size_t)rr[2 * m + 1] * F_IN + kt;
            float2 a0 = __ldg((const float2*)(p0 + cc));
            float2 a1 = __ldg((const float2*)(p1 + cc));
            float2 a2 = __ldg((const float2*)(p0 + cc + 8));
            float2 a3 = __ldg((const float2*)(p1 + cc + 8));
            ah[m][0] = pack_h2(a0.x, a0.y);
            ah[m][1] = pack_h2(a1.x, a1.y);
            ah[m][2] = pack_h2(a2.x, a2.y);
            ah[m][3] = pack_h2(a3.x, a3.y);
        }
        const uint2* wp = g_Wpack + ((size_t)ks * 64 + wid * 8) * 32 + lane;
        #pragma unroll
        for (int j = 0; j < 8; j++) {
            uint2 bp = __ldg(wp + j * 32);
            uint32_t bh[2] = {bp.x, bp.y};
            mma16816(acc[0][j], ah[0], bh);
            mma16816(acc[1][j], ah[1], bh);
        }
    }
    #pragma unroll
    for (int m = 0; m < 2; m++) {
        int row_a = row0 + m * 16 + r;
        int row_b = row_a + 8;
        #pragma unroll
        for (int j = 0; j < 8; j++) {
            int col = wid * 64 + j * 8 + cc;
            if (row_a < N_NODES)
                *(uint32_t*)&g_T[(size_t)row_a * ZTOT + col] = pack_h2(acc[m][j][0], acc[m][j][1]);
            if (row_b < N_NODES)
                *(uint32_t*)&g_T[(size_t)row_b * ZTOT + col] = pack_h2(acc[m][j][2], acc[m][j][3]);
        }
    }
}

// ===================== Clenshaw propagation (64-dim) =======================
// b_out(slot_z) = 2 * L_hat b(slot_g) - b(slot_b2) + Z(slot_z); slot_b2<0 -> 0
__global__ void cheb_kernel(int slot_g, int slot_b2, int slot_z) {
    int warp = blockIdx.x * (blockDim.x >> 5) + (threadIdx.x >> 5);
    if (warp >= N_NODES) return;
    int lane = threadIdx.x & 31;
    int beg = g_rowptr[warp], end = g_rowptr[warp + 1];
    int cg = slot_g * F_OUT + lane * 2;
    float2 acc = make_float2(0.f, 0.f);
    #pragma unroll 2
    for (int e = beg; e < end; e += 4) {
        int2 ed0 = __ldg(&g_edge[e]);
        int2 ed1 = __ldg(&g_edge[e + 1]);
        int2 ed2 = __ldg(&g_edge[e + 2]);
        int2 ed3 = __ldg(&g_edge[e + 3]);
        uint32_t q0 = *(const uint32_t*)(g_T + (size_t)ed0.x * ZTOT + cg);
        uint32_t q1 = *(const uint32_t*)(g_T + (size_t)ed1.x * ZTOT + cg);
        uint32_t q2 = *(const uint32_t*)(g_T + (size_t)ed2.x * ZTOT + cg);
        uint32_t q3 = *(const uint32_t*)(g_T + (size_t)ed3.x * ZTOT + cg);
        float w0 = __int_as_float(ed0.y), w1 = __int_as_float(ed1.y);
        float w2 = __int_as_float(ed2.y), w3 = __int_as_float(ed3.y);
        float2 v0 = unpack_h2(q0), v1 = unpack_h2(q1);
        float2 v2 = unpack_h2(q2), v3 = unpack_h2(q3);
        acc.x += w0 * v0.x + w1 * v1.x + w2 * v2.x + w3 * v3.x;
        acc.y += w0 * v0.y + w1 * v1.y + w2 * v2.y + w3 * v3.y;
    }
    size_t rbase = (size_t)warp * ZTOT;
    float2 z = unpack_h2(*(const uint32_t*)(g_T + rbase + slot_z * F_OUT + lane * 2));
    float2 r;
    if (slot_b2 >= 0) {
        float2 b2 = unpack_h2(*(const uint32_t*)(g_T + rbase + slot_b2 * F_OUT + lane * 2));
        r.x = 2.f * acc.x - b2.x + z.x;
        r.y = 2.f * acc.y - b2.y + z.y;
    } else {
        r.x = 2.f * acc.x + z.x;
        r.y = 2.f * acc.y + z.y;
    }
    *(uint32_t*)(g_T + rbase + slot_z * F_OUT + lane * 2) = pack_h2(r.x, r.y);
}

// out = relu(L_hat b_1 - b_2 + Z_0 + bias), fp32 output
__global__ void final_kernel(const float* __restrict__ bias, float* __restrict__ out) {
    int warp = blockIdx.x * (blockDim.x >> 5) + (threadIdx.x >> 5);
    if (warp >= N_NODES) return;
    int lane = threadIdx.x & 31;
    int beg = g_rowptr[warp], end = g_rowptr[warp + 1];
    int cg = 1 * F_OUT + lane * 2;
    float2 acc = make_float2(0.f, 0.f);
    #pragma unroll 2
    for (int e = beg; e < end; e += 4) {
        int2 ed0 = __ldg(&g_edge[e]);
        int2 ed1 = __ldg(&g_edge[e + 1]);
        int2 ed2 = __ldg(&g_edge[e + 2]);
        int2 ed3 = __ldg(&g_edge[e + 3]);
        uint32_t q0 = *(const uint32_t*)(g_T + (size_t)ed0.x * ZTOT + cg);
        uint32_t q1 = *(const uint32_t*)(g_T + (size_t)ed1.x * ZTOT + cg);
        uint32_t q2 = *(const uint32_t*)(g_T + (size_t)ed2.x * ZTOT + cg);
        uint32_t q3 = *(const uint32_t*)(g_T + (size_t)ed3.x * ZTOT + cg);
        float w0 = __int_as_float(ed0.y), w1 = __int_as_float(ed1.y);
        float w2 = __int_as_float(ed2.y), w3 = __int_as_float(ed3.y);
        float2 v0 = unpack_h2(q0), v1 = unpack_h2(q1);
        float2 v2 = unpack_h2(q2), v3 = unpack_h2(q3);
        acc.x += w0 * v0.x + w1 * v1.x + w2 * v2.x + w3 * v3.x;
        acc.y += w0 * v0.y + w1 * v1.y + w2 * v2.y + w3 * v3.y;
    }
    size_t rbase = (size_t)warp * ZTOT;
    float2 z0 = unpack_h2(*(const uint32_t*)(g_T + rbase + 0 * F_OUT + lane * 2));
    float2 b2 = unpack_h2(*(const uint32_t*)(g_T + rbase + 2 * F_OUT + lane * 2));
    float2 bv = *(const float2*)(bias + lane * 2);
    float2 o;
    o.x = fmaxf(acc.x - b2.x + z0.x + bv.x, 0.f);
    o.y = fmaxf(acc.y - b2.y + z0.y + bv.y, 0.f);
    *(float2*)(out + (size_t)warp * F_OUT + lane * 2) = o;
}

// ---------------------------------------------------------------------------
extern "C" void kernel_launch(void* const* d_in, const int* in_sizes, int n_in,
                              void* d_out, int out_size) {
    const float* x  = (const float*)d_in[0];
    const void*  ei = d_in[1];
    const float* W  = (const float*)d_in[2];
    const float* b  = (const float*)d_in[3];
    float*       out = (float*)d_out;

    init_kernel<<<(N_NODES + 255) / 256, 256>>>((const unsigned int*)ei, W);
    hist_kernel<<<(N_EDGES + 255) / 256, 256>>>(ei);
    scan1_kernel<<<NBLK, SCAN_BLK>>>();
    scanf_kernel<<<NBLK, SCAN_BLK>>>();
    scatter_kernel<<<(N_EDGES + 255) / 256, 256>>>(ei);
    gemmz_kernel<<<GEMM_BLOCKS, 256>>>(x);

    // Clenshaw: b_7 = Z_7 (in place); b_k = 2 L b_{k+1} - b_{k+2} + Z_k
    cheb_kernel<<<(N_NODES + 7) / 8, 256>>>(7, -1, 6);   // k=6 (b_8 = 0)
    cheb_kernel<<<(N_NODES + 7) / 8, 256>>>(6,  7, 5);   // k=5
    cheb_kernel<<<(N_NODES + 7) / 8, 256>>>(5,  6, 4);   // k=4
    cheb_kernel<<<(N_NODES + 7) / 8, 256>>>(4,  5, 3);   // k=3
    cheb_kernel<<<(N_NODES + 7) / 8, 256>>>(3,  4, 2);   // k=2
    cheb_kernel<<<(N_NODES + 7) / 8, 256>>>(2,  3, 1);   // k=1
    final_kernel<<<(N_NODES + 7) / 8, 256>>>(b, out);    // out = L b_1 - b_2 + Z_0
}